// round 1
// baseline (speedup 1.0000x reference)
#include <cuda_runtime.h>
#include <cstdint>

#define TT 4
#define BBATCH 32
#define CC 384
#define NN 196
#define MM 6272            // BBATCH*NN
#define HH 8
#define DD 48
#define DQKV 1152
#define TSTR (BBATCH*CC*NN)    // 2408448
#define MASKN (TT*BBATCH*HH*NN)  // 200704

// ---------------- scratch (device globals; no allocation allowed) ----------------
__device__ __align__(16) unsigned char g_spk[TT*MM*DQKV];            // 28.9 MB spike bytes (q|k|v)
__device__ unsigned long long g_mask[3*MASKN];                        // bit-packed spikes
__device__ float g_attnspk[TT*BBATCH*CC*NN];                          // attn-LIF spikes (conv4 input)
__device__ float g_Wt1152[CC*DQKV];                                   // transposed fused qkv weights [C][1152]
__device__ float g_Wt384[CC*CC];                                      // transposed wp [C][384]

// ---------------- weight transpose prep ----------------
__global__ void k_prepw(const float* __restrict__ wq, const float* __restrict__ wk,
                        const float* __restrict__ wv, const float* __restrict__ wp) {
    int i = blockIdx.x * 256 + threadIdx.x;
    if (i < CC*DQKV) {
        int c = i / DQKV, dg = i - c*DQKV;
        int ten = dg / CC, d = dg - ten*CC;
        const float* w = (ten == 0) ? wq : (ten == 1) ? wk : wv;
        g_Wt1152[i] = w[d*CC + c];
    } else {
        int k = i - CC*DQKV;
        if (k < CC*CC) {
            int c = k / CC, d = k - c*CC;
            g_Wt384[k] = wp[d*CC + c];
        }
    }
}

// ---------------- fused conv(1x1) + BN + LIF GEMM ----------------
// A[t][b][c][n] fp32, W transposed [C][DTOT]. BM=64 (positions), BN=64 (out ch),
// BK=16, 256 threads, 4x4 thread tile, all 4 time steps accumulated per thread
// so LIF fuses into the epilogue. Double-buffered smem.
template<bool FINAL>
__global__ void __launch_bounds__(256, 2) k_conv_lif(
    const float* __restrict__ X,
    const float* __restrict__ sc0, const float* __restrict__ sc1, const float* __restrict__ sc2,
    const float* __restrict__ bi0, const float* __restrict__ bi1, const float* __restrict__ bi2,
    float* __restrict__ outF)
{
    constexpr int DTOT = FINAL ? CC : DQKV;
    const float* __restrict__ A  = FINAL ? g_attnspk : X;
    const float* __restrict__ Wt = FINAL ? g_Wt384 : g_Wt1152;

    __shared__ __align__(16) float As[2][TT][16][64];
    __shared__ __align__(16) float Ws[2][16][64];

    const int tid = threadIdx.x;
    const int m0 = blockIdx.x * 64;
    const int d0 = blockIdx.y * 64;

    // loader coords: 64 m-columns x 4 k-rows per thread-group
    const int lm = tid & 63, lk = tid >> 6;
    const int mg = m0 + lm;
    const int lb = mg / NN;
    const int ln = mg - lb * NN;
    const float* Ap = A + (size_t)lb * CC * NN + ln;

    float acc[TT][16];
    #pragma unroll
    for (int t = 0; t < TT; t++)
        #pragma unroll
        for (int u = 0; u < 16; u++) acc[t][u] = 0.f;

    float ra[TT][4], rw[4];

    // prologue: load k-tile 0
    #pragma unroll
    for (int t = 0; t < TT; t++)
        #pragma unroll
        for (int i = 0; i < 4; i++)
            ra[t][i] = Ap[(size_t)t*TSTR + (size_t)(lk + i*4)*NN];
    #pragma unroll
    for (int i = 0; i < 4; i++) {
        int e = tid + i*256;
        rw[i] = Wt[(size_t)(e >> 6)*DTOT + d0 + (e & 63)];
    }
    #pragma unroll
    for (int t = 0; t < TT; t++)
        #pragma unroll
        for (int i = 0; i < 4; i++)
            As[0][t][lk + i*4][lm] = ra[t][i];
    #pragma unroll
    for (int i = 0; i < 4; i++) { int e = tid + i*256; Ws[0][e >> 6][e & 63] = rw[i]; }
    __syncthreads();

    const int tx4 = (tid & 15) * 4, ty4 = (tid >> 4) * 4;
    int buf = 0;
    for (int kt = 0; kt < 24; kt++) {
        if (kt < 23) {
            int c0 = (kt + 1) * 16;
            #pragma unroll
            for (int t = 0; t < TT; t++)
                #pragma unroll
                for (int i = 0; i < 4; i++)
                    ra[t][i] = Ap[(size_t)t*TSTR + (size_t)(c0 + lk + i*4)*NN];
            #pragma unroll
            for (int i = 0; i < 4; i++) {
                int e = tid + i*256;
                rw[i] = Wt[(size_t)(c0 + (e >> 6))*DTOT + d0 + (e & 63)];
            }
        }
        #pragma unroll
        for (int k = 0; k < 16; k++) {
            float4 bfv = *(const float4*)&Ws[buf][k][tx4];
            float bf[4] = {bfv.x, bfv.y, bfv.z, bfv.w};
            #pragma unroll
            for (int t = 0; t < TT; t++) {
                float4 afv = *(const float4*)&As[buf][t][k][ty4];
                float af[4] = {afv.x, afv.y, afv.z, afv.w};
                #pragma unroll
                for (int i = 0; i < 4; i++)
                    #pragma unroll
                    for (int j = 0; j < 4; j++)
                        acc[t][i*4 + j] = fmaf(af[i], bf[j], acc[t][i*4 + j]);
            }
        }
        if (kt < 23) {
            int nb = buf ^ 1;
            #pragma unroll
            for (int t = 0; t < TT; t++)
                #pragma unroll
                for (int i = 0; i < 4; i++)
                    As[nb][t][lk + i*4][lm] = ra[t][i];
            #pragma unroll
            for (int i = 0; i < 4; i++) { int e = tid + i*256; Ws[nb][e >> 6][e & 63] = rw[i]; }
        }
        __syncthreads();
        buf ^= 1;
    }

    // ---- epilogue: BN + LIF (exact op sequence of reference; no fma contraction) ----
    const int tx = tid & 15, ty = tid >> 4;
    int dl = d0 + tx*4;               // channel within its tensor
    const float *sc, *bi;
    if (FINAL) { sc = sc0; bi = bi0; }
    else {
        int ten = d0 / CC;
        dl = d0 - ten*CC + tx*4;
        sc = (ten == 0) ? sc0 : (ten == 1) ? sc1 : sc2;
        bi = (ten == 0) ? bi0 : (ten == 1) ? bi1 : bi2;
    }
    float scv[4], biv[4];
    #pragma unroll
    for (int j = 0; j < 4; j++) { scv[j] = sc[dl + j]; biv[j] = bi[dl + j]; }

    #pragma unroll
    for (int i = 0; i < 4; i++) {
        int m = m0 + ty*4 + i;
        float v[4] = {0.f, 0.f, 0.f, 0.f};
        if (!FINAL) {
            #pragma unroll
            for (int t = 0; t < TT; t++) {
                unsigned pk = 0;
                #pragma unroll
                for (int j = 0; j < 4; j++) {
                    float y = __fadd_rn(__fmul_rn(acc[t][i*4 + j], scv[j]), biv[j]);
                    v[j] = __fadd_rn(v[j], __fmul_rn(__fadd_rn(y, -v[j]), 0.5f));
                    if (v[j] >= 1.0f) { pk |= 1u << (8*j); v[j] = 0.f; }
                }
                *(unsigned*)&g_spk[((size_t)t*MM + m)*DQKV + d0 + tx*4] = pk;
            }
        } else {
            int b_o = m / NN, n_o = m - b_o*NN;
            #pragma unroll
            for (int t = 0; t < TT; t++) {
                #pragma unroll
                for (int j = 0; j < 4; j++) {
                    float y = __fadd_rn(__fmul_rn(acc[t][i*4 + j], scv[j]), biv[j]);
                    v[j] = __fadd_rn(v[j], __fmul_rn(__fadd_rn(y, -v[j]), 0.5f));
                    bool hh = v[j] >= 1.0f;
                    outF[(((size_t)t*BBATCH + b_o)*CC + (dl + j))*NN + n_o] = hh ? 1.0f : 0.0f;
                    if (hh) v[j] = 0.f;
                }
            }
        }
    }
}

// ---------------- bit-pack spikes: 48 bytes -> uint64 per (tensor,t,b,h,n) ----------------
__global__ void k_pack() {
    int w = blockIdx.x * 256 + threadIdx.x;   // exactly 3*MASKN threads launched
    int ten = w / MASKN;
    int r = w - ten*MASKN;
    int n = r % NN;
    int q1 = r / NN;
    int h = q1 % HH;
    int q2 = q1 / HH;
    int bb = q2 % BBATCH;
    int t = q2 / BBATCH;
    int m = bb*NN + n;
    size_t base = ((size_t)t*MM + m)*DQKV + ten*CC + h*DD;   // 16B aligned
    const uint4* p = (const uint4*)(g_spk + base);
    unsigned long long mask = 0;
    int bit = 0;
    #pragma unroll
    for (int q = 0; q < 3; q++) {
        uint4 u = p[q];
        unsigned wds[4] = {u.x, u.y, u.z, u.w};
        #pragma unroll
        for (int k = 0; k < 4; k++) {
            unsigned uu = wds[k];
            unsigned nib = (uu & 1u) | ((uu >> 7) & 2u) | ((uu >> 14) & 4u) | ((uu >> 21) & 8u);
            mask |= (unsigned long long)nib << bit;
            bit += 4;
        }
    }
    g_mask[(size_t)ten*MASKN + r] = mask;
}

// ---------------- attention: out = q @ (k^T v) * 0.125, then LIF(0.5) ----------------
// Integer-exact: spikes binary, G entries <=196, sums <=9408 < 2^24.
__global__ void __launch_bounds__(256) k_attn() {
    __shared__ unsigned long long qm[TT][NN];
    __shared__ unsigned long long km[TT][NN];
    __shared__ unsigned long long vm[TT][NN];
    __shared__ unsigned int kT[TT][DD][7];
    __shared__ unsigned int vT[TT][DD][7];
    __shared__ unsigned short G[TT][DD][DD];

    const int b = blockIdx.x, h = blockIdx.y;
    const int tid = threadIdx.x;

    for (int e = tid; e < TT*NN; e += 256) {
        int t = e / NN, n = e - t*NN;
        size_t idx = ((size_t)(t*BBATCH + b)*HH + h)*NN + n;
        qm[t][n] = g_mask[idx];
        km[t][n] = g_mask[(size_t)MASKN + idx];
        vm[t][n] = g_mask[2*(size_t)MASKN + idx];
    }
    __syncthreads();

    // bit-transpose k,v via warp ballot: 8 warps = 4 t x {k,v}
    {
        int w = tid >> 5, lane = tid & 31;
        int t = w >> 1;
        int isv = w & 1;
        for (int g = 0; g < 7; g++) {
            int m = g*32 + lane;
            unsigned long long mk = 0;
            if (m < NN) mk = isv ? vm[t][m] : km[t][m];
            #pragma unroll
            for (int j = 0; j < DD; j++) {
                unsigned bal = __ballot_sync(0xffffffffu, (unsigned)((mk >> j) & 1ull));
                if (lane == 0) { if (isv) vT[t][j][g] = bal; else kT[t][j][g] = bal; }
            }
        }
    }
    __syncthreads();

    // G[t][j][d] = sum_m k[m,j] v[m,d]  via AND+popc over 196-bit rows
    for (int e = tid; e < TT*DD*DD; e += 256) {
        int t = e / (DD*DD), r = e - t*(DD*DD);
        int j = r / DD, d = r - j*DD;
        int s = 0;
        #pragma unroll
        for (int g = 0; g < 7; g++) s += __popc(kT[t][j][g] & vT[t][d][g]);
        G[t][j][d] = (unsigned short)s;
    }
    __syncthreads();

    // out[n,d] = 0.125 * sum_j q[n,j] G[j,d]; fuse LIF(v_th=0.5) over t; write fp32 spikes
    for (int e = tid; e < DD*NN; e += 256) {
        int d = e / NN, n = e - d*NN;
        float v = 0.f;
        #pragma unroll
        for (int t = 0; t < TT; t++) {
            unsigned long long q = qm[t][n];
            int S = 0;
            #pragma unroll
            for (int j = 0; j < DD; j++)
                S += ((int)(q >> j) & 1) * (int)G[t][j][d];
            float x = (float)S * 0.125f;
            v = __fadd_rn(v, __fmul_rn(__fadd_rn(x, -v), 0.5f));
            bool hh = v >= 0.5f;
            g_attnspk[(((size_t)t*BBATCH + b)*CC + h*DD + d)*NN + n] = hh ? 1.0f : 0.0f;
            if (hh) v = 0.f;
        }
    }
}

// ---------------- launch ----------------
extern "C" void kernel_launch(void* const* d_in, const int* in_sizes, int n_in,
                              void* d_out, int out_size) {
    const float* x  = (const float*)d_in[0];
    const float* wq = (const float*)d_in[1];
    const float* sq = (const float*)d_in[2];
    const float* bq = (const float*)d_in[3];
    const float* wk = (const float*)d_in[4];
    const float* sk = (const float*)d_in[5];
    const float* bk = (const float*)d_in[6];
    const float* wv = (const float*)d_in[7];
    const float* sv = (const float*)d_in[8];
    const float* bv = (const float*)d_in[9];
    const float* wp = (const float*)d_in[10];
    const float* sp = (const float*)d_in[11];
    const float* bp = (const float*)d_in[12];
    float* out = (float*)d_out;

    k_prepw<<<(CC*DQKV + CC*CC + 255)/256, 256>>>(wq, wk, wv, wp);
    k_conv_lif<false><<<dim3(98, 18), 256>>>(x, sq, sk, sv, bq, bk, bv, nullptr);
    k_pack<<<(3*MASKN)/256, 256>>>();
    k_attn<<<dim3(BBATCH, HH), 256>>>();
    k_conv_lif<true><<<dim3(98, 6), 256>>>(x, sp, sp, sp, bp, bp, bp, out);
}

// round 2
// speedup vs baseline: 1.1902x; 1.1902x over previous
#include <cuda_runtime.h>
#include <cstdint>

#define TT 4
#define BBATCH 32
#define CC 384
#define NN 196
#define MM 6272            // BBATCH*NN
#define HH 8
#define DD 48
#define DQKV 1152
#define TSTR (BBATCH*CC*NN)    // 2408448
#define MASKN (TT*BBATCH*HH*NN)  // 200704

typedef unsigned long long u64;
typedef unsigned int u32;

// packed f32x2 helpers (sm_103a FFMA2 only reachable via PTX)
#define FMA_F32X2(d, a, b) \
    asm("fma.rn.f32x2 %0, %1, %2, %3;" : "=l"(d) : "l"(a), "l"(b), "l"(d))
#define DUP_F32X2(d, f) \
    asm("mov.b64 %0, {%1, %1};" : "=l"(d) : "r"(__float_as_uint(f)))
#define UNPACK_F32X2(lo, hi, v) \
    asm("mov.b64 {%0, %1}, %2;" : "=r"(lo), "=r"(hi) : "l"(v))

// ---------------- scratch (device globals; no allocation allowed) ----------------
__device__ __align__(16) unsigned char g_spk[TT*MM*DQKV];            // spike bytes (q|k|v)
__device__ unsigned long long g_mask[3*MASKN];                        // bit-packed spikes
__device__ float g_attnspk[TT*BBATCH*CC*NN];                          // attn-LIF spikes
__device__ float g_Wt1152[CC*DQKV];                                   // transposed qkv weights [C][1152]
__device__ float g_Wt384[CC*CC];                                      // transposed wp [C][384]

// ---------------- weight transpose prep ----------------
__global__ void k_prepw(const float* __restrict__ wq, const float* __restrict__ wk,
                        const float* __restrict__ wv, const float* __restrict__ wp) {
    int i = blockIdx.x * 256 + threadIdx.x;
    if (i < CC*DQKV) {
        int c = i / DQKV, dg = i - c*DQKV;
        int ten = dg / CC, d = dg - ten*CC;
        const float* w = (ten == 0) ? wq : (ten == 1) ? wk : wv;
        g_Wt1152[i] = w[d*CC + c];
    } else {
        int k = i - CC*DQKV;
        if (k < CC*CC) {
            int c = k / CC, d = k - c*CC;
            g_Wt384[k] = wp[d*CC + c];
        }
    }
}

// ---------------- fused conv(1x1) + BN + LIF GEMM (FFMA2) ----------------
// BM=64 (positions), BN=64 (out ch), BK=16, 256 threads, 4x4 thread tile with
// the 4 m-rows held as two f32x2 lane-pairs. All 4 time steps per thread so
// LIF fuses into the epilogue. Per-accumulator k-order identical to scalar
// version -> bit-identical outputs.
template<bool FINAL>
__global__ void __launch_bounds__(256, 2) k_conv_lif(
    const float* __restrict__ X,
    const float* __restrict__ sc0, const float* __restrict__ sc1, const float* __restrict__ sc2,
    const float* __restrict__ bi0, const float* __restrict__ bi1, const float* __restrict__ bi2,
    float* __restrict__ outF)
{
    constexpr int DTOT = FINAL ? CC : DQKV;
    const float* __restrict__ A  = FINAL ? g_attnspk : X;
    const float* __restrict__ Wt = FINAL ? g_Wt384 : g_Wt1152;

    __shared__ __align__(16) float As[2][TT][16][64];
    __shared__ __align__(16) float Ws[2][16][64];

    const int tid = threadIdx.x;
    const int m0 = blockIdx.x * 64;
    const int d0 = blockIdx.y * 64;

    const int lm = tid & 63, lk = tid >> 6;
    const int mg = m0 + lm;
    const int lb = mg / NN;
    const int ln = mg - lb * NN;
    const float* Ap = A + (size_t)lb * CC * NN + ln;

    // acc2[t][ipair][j] : lane0 = m-row 2*ipair, lane1 = m-row 2*ipair+1
    u64 acc2[TT][2][4];
    #pragma unroll
    for (int t = 0; t < TT; t++)
        #pragma unroll
        for (int p = 0; p < 2; p++)
            #pragma unroll
            for (int j = 0; j < 4; j++) acc2[t][p][j] = 0ull;

    float ra[TT][4], rw[4];

    // prologue: load k-tile 0
    #pragma unroll
    for (int t = 0; t < TT; t++)
        #pragma unroll
        for (int i = 0; i < 4; i++)
            ra[t][i] = Ap[(size_t)t*TSTR + (size_t)(lk + i*4)*NN];
    #pragma unroll
    for (int i = 0; i < 4; i++) {
        int e = tid + i*256;
        rw[i] = Wt[(size_t)(e >> 6)*DTOT + d0 + (e & 63)];
    }
    #pragma unroll
    for (int t = 0; t < TT; t++)
        #pragma unroll
        for (int i = 0; i < 4; i++)
            As[0][t][lk + i*4][lm] = ra[t][i];
    #pragma unroll
    for (int i = 0; i < 4; i++) { int e = tid + i*256; Ws[0][e >> 6][e & 63] = rw[i]; }
    __syncthreads();

    const int tx4 = (tid & 15) * 4, ty4 = (tid >> 4) * 4;
    int buf = 0;
    for (int kt = 0; kt < 24; kt++) {
        if (kt < 23) {
            int c0 = (kt + 1) * 16;
            #pragma unroll
            for (int t = 0; t < TT; t++)
                #pragma unroll
                for (int i = 0; i < 4; i++)
                    ra[t][i] = Ap[(size_t)t*TSTR + (size_t)(c0 + lk + i*4)*NN];
            #pragma unroll
            for (int i = 0; i < 4; i++) {
                int e = tid + i*256;
                rw[i] = Wt[(size_t)(c0 + (e >> 6))*DTOT + d0 + (e & 63)];
            }
        }
        #pragma unroll
        for (int k = 0; k < 16; k++) {
            float4 bfv = *(const float4*)&Ws[buf][k][tx4];
            u64 b2[4];
            DUP_F32X2(b2[0], bfv.x);
            DUP_F32X2(b2[1], bfv.y);
            DUP_F32X2(b2[2], bfv.z);
            DUP_F32X2(b2[3], bfv.w);
            #pragma unroll
            for (int t = 0; t < TT; t++) {
                u64 a01 = *(const u64*)&As[buf][t][k][ty4];
                u64 a23 = *(const u64*)&As[buf][t][k][ty4 + 2];
                #pragma unroll
                for (int j = 0; j < 4; j++) {
                    FMA_F32X2(acc2[t][0][j], a01, b2[j]);
                    FMA_F32X2(acc2[t][1][j], a23, b2[j]);
                }
            }
        }
        if (kt < 23) {
            int nb = buf ^ 1;
            #pragma unroll
            for (int t = 0; t < TT; t++)
                #pragma unroll
                for (int i = 0; i < 4; i++)
                    As[nb][t][lk + i*4][lm] = ra[t][i];
            #pragma unroll
            for (int i = 0; i < 4; i++) { int e = tid + i*256; Ws[nb][e >> 6][e & 63] = rw[i]; }
        }
        __syncthreads();
        buf ^= 1;
    }

    // unpack to scalar layout acc[t][i*4+j]
    float acc[TT][16];
    #pragma unroll
    for (int t = 0; t < TT; t++)
        #pragma unroll
        for (int p = 0; p < 2; p++)
            #pragma unroll
            for (int j = 0; j < 4; j++) {
                u32 lo, hi;
                UNPACK_F32X2(lo, hi, acc2[t][p][j]);
                acc[t][(2*p)*4 + j]     = __uint_as_float(lo);
                acc[t][(2*p + 1)*4 + j] = __uint_as_float(hi);
            }

    // ---- epilogue: BN + LIF (exact op sequence of reference; no fma contraction) ----
    const int tx = tid & 15, ty = tid >> 4;
    int dl = d0 + tx*4;
    const float *sc, *bi;
    if (FINAL) { sc = sc0; bi = bi0; }
    else {
        int ten = d0 / CC;
        dl = d0 - ten*CC + tx*4;
        sc = (ten == 0) ? sc0 : (ten == 1) ? sc1 : sc2;
        bi = (ten == 0) ? bi0 : (ten == 1) ? bi1 : bi2;
    }
    float scv[4], biv[4];
    #pragma unroll
    for (int j = 0; j < 4; j++) { scv[j] = sc[dl + j]; biv[j] = bi[dl + j]; }

    #pragma unroll
    for (int i = 0; i < 4; i++) {
        int m = m0 + ty*4 + i;
        float v[4] = {0.f, 0.f, 0.f, 0.f};
        if (!FINAL) {
            #pragma unroll
            for (int t = 0; t < TT; t++) {
                unsigned pk = 0;
                #pragma unroll
                for (int j = 0; j < 4; j++) {
                    float y = __fadd_rn(__fmul_rn(acc[t][i*4 + j], scv[j]), biv[j]);
                    v[j] = __fadd_rn(v[j], __fmul_rn(__fadd_rn(y, -v[j]), 0.5f));
                    if (v[j] >= 1.0f) { pk |= 1u << (8*j); v[j] = 0.f; }
                }
                *(unsigned*)&g_spk[((size_t)t*MM + m)*DQKV + d0 + tx*4] = pk;
            }
        } else {
            int b_o = m / NN, n_o = m - b_o*NN;
            #pragma unroll
            for (int t = 0; t < TT; t++) {
                #pragma unroll
                for (int j = 0; j < 4; j++) {
                    float y = __fadd_rn(__fmul_rn(acc[t][i*4 + j], scv[j]), biv[j]);
                    v[j] = __fadd_rn(v[j], __fmul_rn(__fadd_rn(y, -v[j]), 0.5f));
                    bool hh = v[j] >= 1.0f;
                    outF[(((size_t)t*BBATCH + b_o)*CC + (dl + j))*NN + n_o] = hh ? 1.0f : 0.0f;
                    if (hh) v[j] = 0.f;
                }
            }
        }
    }
}

// ---------------- bit-pack spikes: 48 bytes -> uint64 per (tensor,t,b,h,n) ----------------
__global__ void k_pack() {
    int w = blockIdx.x * 256 + threadIdx.x;
    int ten = w / MASKN;
    int r = w - ten*MASKN;
    int n = r % NN;
    int q1 = r / NN;
    int h = q1 % HH;
    int q2 = q1 / HH;
    int bb = q2 % BBATCH;
    int t = q2 / BBATCH;
    int m = bb*NN + n;
    size_t base = ((size_t)t*MM + m)*DQKV + ten*CC + h*DD;
    const uint4* p = (const uint4*)(g_spk + base);
    unsigned long long mask = 0;
    int bit = 0;
    #pragma unroll
    for (int q = 0; q < 3; q++) {
        uint4 u = p[q];
        unsigned wds[4] = {u.x, u.y, u.z, u.w};
        #pragma unroll
        for (int k = 0; k < 4; k++) {
            unsigned uu = wds[k];
            unsigned nib = (uu & 1u) | ((uu >> 7) & 2u) | ((uu >> 14) & 4u) | ((uu >> 21) & 8u);
            mask |= (unsigned long long)nib << bit;
            bit += 4;
        }
    }
    g_mask[(size_t)ten*MASKN + r] = mask;
}

// ---------------- attention: out = q @ (k^T v) * 0.125, then LIF(0.5) ----------------
// Integer-exact: spikes binary, G entries <=196, sums <=9408 < 2^16 (no carry
// between packed u16 lanes).
__global__ void __launch_bounds__(256) k_attn() {
    __shared__ unsigned long long qm[TT][NN];
    __shared__ unsigned long long km[TT][NN];
    __shared__ unsigned long long vm[TT][NN];
    __shared__ unsigned int kT[TT][DD][7];
    __shared__ unsigned int vT[TT][DD][7];
    __shared__ __align__(16) unsigned int Gp[TT][DD][24];   // two u16 sums per word (d even|odd)

    const int b = blockIdx.x, h = blockIdx.y;
    const int tid = threadIdx.x;

    for (int e = tid; e < TT*NN; e += 256) {
        int t = e / NN, n = e - t*NN;
        size_t idx = ((size_t)(t*BBATCH + b)*HH + h)*NN + n;
        qm[t][n] = g_mask[idx];
        km[t][n] = g_mask[(size_t)MASKN + idx];
        vm[t][n] = g_mask[2*(size_t)MASKN + idx];
    }
    __syncthreads();

    // bit-transpose k,v via warp ballot: 8 warps = 4 t x {k,v}
    {
        int w = tid >> 5, lane = tid & 31;
        int t = w >> 1;
        int isv = w & 1;
        for (int g = 0; g < 7; g++) {
            int m = g*32 + lane;
            unsigned long long mk = 0;
            if (m < NN) mk = isv ? vm[t][m] : km[t][m];
            #pragma unroll
            for (int j = 0; j < DD; j++) {
                unsigned bal = __ballot_sync(0xffffffffu, (unsigned)((mk >> j) & 1ull));
                if (lane == 0) { if (isv) vT[t][j][g] = bal; else kT[t][j][g] = bal; }
            }
        }
    }
    __syncthreads();

    // Gp[t][j][p] = G[j][2p] | G[j][2p+1]<<16 via AND+popc over 196-bit rows
    for (int e = tid; e < TT*DD*24; e += 256) {
        int t = e / (DD*24), r = e - t*(DD*24);
        int j = r / 24, p = r - j*24;
        int s0 = 0, s1 = 0;
        #pragma unroll
        for (int g = 0; g < 7; g++) {
            s0 += __popc(kT[t][j][g] & vT[t][2*p][g]);
            s1 += __popc(kT[t][j][g] & vT[t][2*p + 1][g]);
        }
        Gp[t][j][p] = (unsigned)s0 | ((unsigned)s1 << 16);
    }
    __syncthreads();

    // out[n, 8g..8g+7]: masked packed adds over j; LIF(0.5) over t; write fp32 spikes
    for (int e = tid; e < 6*NN; e += 256) {
        int g = e / NN, n = e - g*NN;
        int p0 = g * 4;                    // pairs p0..p0+3 -> d = 8g..8g+7
        float v[8];
        #pragma unroll
        for (int d = 0; d < 8; d++) v[d] = 0.f;
        #pragma unroll
        for (int t = 0; t < TT; t++) {
            unsigned long long q = qm[t][n];
            unsigned ql = (unsigned)q, qh = (unsigned)(q >> 32);
            unsigned S[4] = {0u, 0u, 0u, 0u};
            #pragma unroll
            for (int j = 0; j < 32; j++) {
                unsigned msk = 0u - ((ql >> j) & 1u);
                uint4 gw = *(const uint4*)&Gp[t][j][p0];
                S[0] += gw.x & msk; S[1] += gw.y & msk;
                S[2] += gw.z & msk; S[3] += gw.w & msk;
            }
            #pragma unroll
            for (int j = 0; j < 16; j++) {
                unsigned msk = 0u - ((qh >> j) & 1u);
                uint4 gw = *(const uint4*)&Gp[t][32 + j][p0];
                S[0] += gw.x & msk; S[1] += gw.y & msk;
                S[2] += gw.z & msk; S[3] += gw.w & msk;
            }
            float* outp = &g_attnspk[(((size_t)t*BBATCH + b)*CC + h*DD + 8*g)*NN + n];
            #pragma unroll
            for (int pp = 0; pp < 4; pp++) {
                int s0 = (int)(S[pp] & 0xFFFFu);
                int s1 = (int)(S[pp] >> 16);
                float x0 = (float)s0 * 0.125f;
                float x1 = (float)s1 * 0.125f;
                int d0i = 2*pp, d1i = 2*pp + 1;
                v[d0i] = __fadd_rn(v[d0i], __fmul_rn(__fadd_rn(x0, -v[d0i]), 0.5f));
                v[d1i] = __fadd_rn(v[d1i], __fmul_rn(__fadd_rn(x1, -v[d1i]), 0.5f));
                bool h0 = v[d0i] >= 0.5f, h1 = v[d1i] >= 0.5f;
                outp[(size_t)d0i * NN] = h0 ? 1.0f : 0.0f;
                outp[(size_t)d1i * NN] = h1 ? 1.0f : 0.0f;
                if (h0) v[d0i] = 0.f;
                if (h1) v[d1i] = 0.f;
            }
        }
    }
}

// ---------------- launch ----------------
extern "C" void kernel_launch(void* const* d_in, const int* in_sizes, int n_in,
                              void* d_out, int out_size) {
    const float* x  = (const float*)d_in[0];
    const float* wq = (const float*)d_in[1];
    const float* sq = (const float*)d_in[2];
    const float* bq = (const float*)d_in[3];
    const float* wk = (const float*)d_in[4];
    const float* sk = (const float*)d_in[5];
    const float* bk = (const float*)d_in[6];
    const float* wv = (const float*)d_in[7];
    const float* sv = (const float*)d_in[8];
    const float* bv = (const float*)d_in[9];
    const float* wp = (const float*)d_in[10];
    const float* sp = (const float*)d_in[11];
    const float* bp = (const float*)d_in[12];
    float* out = (float*)d_out;

    k_prepw<<<(CC*DQKV + CC*CC + 255)/256, 256>>>(wq, wk, wv, wp);
    k_conv_lif<false><<<dim3(98, 18), 256>>>(x, sq, sk, sv, bq, bk, bv, nullptr);
    k_pack<<<(3*MASKN)/256, 256>>>();
    k_attn<<<dim3(BBATCH, HH), 256>>>();
    k_conv_lif<true><<<dim3(98, 6), 256>>>(x, sp, sp, sp, bp, bp, bp, out);
}

// round 5
// speedup vs baseline: 1.2100x; 1.0166x over previous
#include <cuda_runtime.h>
#include <cstdint>

#define TT 4
#define BBATCH 32
#define CC 384
#define NN 196
#define MM 6272            // BBATCH*NN
#define HH 8
#define DD 48
#define DQKV 1152
#define TSTR (BBATCH*CC*NN)    // 2408448
#define MASKN (TT*BBATCH*HH*NN)  // 200704

typedef unsigned long long u64;
typedef unsigned int u32;

// packed f32x2 helpers (sm_103a FFMA2 only reachable via PTX)
#define FMA_F32X2(d, a, b) \
    asm("fma.rn.f32x2 %0, %1, %2, %3;" : "=l"(d) : "l"(a), "l"(b), "l"(d))
#define DUP_F32X2(d, f) \
    asm("mov.b64 %0, {%1, %1};" : "=l"(d) : "r"(__float_as_uint(f)))
#define UNPACK_F32X2(lo, hi, v) \
    asm("mov.b64 {%0, %1}, %2;" : "=r"(lo), "=r"(hi) : "l"(v))

// ---------------- scratch (device globals; no allocation allowed) ----------------
__device__ __align__(16) unsigned char g_spk[TT*MM*DQKV];            // spike bytes (q|k|v)
__device__ float g_attnspk[TT*BBATCH*CC*NN];                          // attn-LIF spikes
__device__ float g_Wt1152[CC*DQKV];                                   // transposed qkv weights [C][1152]
__device__ float g_Wt384[CC*CC];                                      // transposed wp [C][384]

// ---------------- weight transpose prep ----------------
__global__ void k_prepw(const float* __restrict__ wq, const float* __restrict__ wk,
                        const float* __restrict__ wv, const float* __restrict__ wp) {
    int i = blockIdx.x * 256 + threadIdx.x;
    if (i < CC*DQKV) {
        int c = i / DQKV, dg = i - c*DQKV;
        int ten = dg / CC, d = dg - ten*CC;
        const float* w = (ten == 0) ? wq : (ten == 1) ? wk : wv;
        g_Wt1152[i] = w[d*CC + c];
    } else {
        int k = i - CC*DQKV;
        if (k < CC*CC) {
            int c = k / CC, d = k - c*CC;
            g_Wt384[k] = wp[d*CC + c];
        }
    }
}

// ---------------- fused conv(1x1) + BN + LIF GEMM (FFMA2) ----------------
// BM=64, BN=64, BK=16, 256 threads, 4x4 thread tile as two f32x2 m-pairs,
// all 4 time steps per thread so LIF fuses into the epilogue.
// Per-accumulator k-order identical to scalar -> bit-identical outputs.
template<bool FINAL>
__global__ void __launch_bounds__(256, 2) k_conv_lif(
    const float* __restrict__ X,
    const float* __restrict__ sc0, const float* __restrict__ sc1, const float* __restrict__ sc2,
    const float* __restrict__ bi0, const float* __restrict__ bi1, const float* __restrict__ bi2,
    float* __restrict__ outF)
{
    constexpr int DTOT = FINAL ? CC : DQKV;
    const float* __restrict__ A  = FINAL ? g_attnspk : X;
    const float* __restrict__ Wt = FINAL ? g_Wt384 : g_Wt1152;

    __shared__ __align__(16) float As[2][TT][16][64];
    __shared__ __align__(16) float Ws[2][16][64];

    const int tid = threadIdx.x;
    const int m0 = blockIdx.x * 64;
    const int d0 = blockIdx.y * 64;

    const int lm = tid & 63, lk = tid >> 6;
    const int mg = m0 + lm;
    const int lb = mg / NN;
    const int ln = mg - lb * NN;
    const float* Ap = A + (size_t)lb * CC * NN + ln;

    // acc2[t][ipair][j] : lane0 = m-row 2*ipair, lane1 = m-row 2*ipair+1
    u64 acc2[TT][2][4];
    #pragma unroll
    for (int t = 0; t < TT; t++)
        #pragma unroll
        for (int p = 0; p < 2; p++)
            #pragma unroll
            for (int j = 0; j < 4; j++) acc2[t][p][j] = 0ull;

    float ra[TT][4], rw[4];

    // prologue: load k-tile 0
    #pragma unroll
    for (int t = 0; t < TT; t++)
        #pragma unroll
        for (int i = 0; i < 4; i++)
            ra[t][i] = Ap[(size_t)t*TSTR + (size_t)(lk + i*4)*NN];
    #pragma unroll
    for (int i = 0; i < 4; i++) {
        int e = tid + i*256;
        rw[i] = Wt[(size_t)(e >> 6)*DTOT + d0 + (e & 63)];
    }
    #pragma unroll
    for (int t = 0; t < TT; t++)
        #pragma unroll
        for (int i = 0; i < 4; i++)
            As[0][t][lk + i*4][lm] = ra[t][i];
    #pragma unroll
    for (int i = 0; i < 4; i++) { int e = tid + i*256; Ws[0][e >> 6][e & 63] = rw[i]; }
    __syncthreads();

    const int tx4 = (tid & 15) * 4, ty4 = (tid >> 4) * 4;
    int buf = 0;
    for (int kt = 0; kt < 24; kt++) {
        if (kt < 23) {
            int c0 = (kt + 1) * 16;
            #pragma unroll
            for (int t = 0; t < TT; t++)
                #pragma unroll
                for (int i = 0; i < 4; i++)
                    ra[t][i] = Ap[(size_t)t*TSTR + (size_t)(c0 + lk + i*4)*NN];
            #pragma unroll
            for (int i = 0; i < 4; i++) {
                int e = tid + i*256;
                rw[i] = Wt[(size_t)(c0 + (e >> 6))*DTOT + d0 + (e & 63)];
            }
        }
        #pragma unroll
        for (int k = 0; k < 16; k++) {
            float4 bfv = *(const float4*)&Ws[buf][k][tx4];
            u64 b2[4];
            DUP_F32X2(b2[0], bfv.x);
            DUP_F32X2(b2[1], bfv.y);
            DUP_F32X2(b2[2], bfv.z);
            DUP_F32X2(b2[3], bfv.w);
            #pragma unroll
            for (int t = 0; t < TT; t++) {
                ulonglong2 av = *(const ulonglong2*)&As[buf][t][k][ty4];
                #pragma unroll
                for (int j = 0; j < 4; j++) {
                    FMA_F32X2(acc2[t][0][j], av.x, b2[j]);
                    FMA_F32X2(acc2[t][1][j], av.y, b2[j]);
                }
            }
        }
        if (kt < 23) {
            int nb = buf ^ 1;
            #pragma unroll
            for (int t = 0; t < TT; t++)
                #pragma unroll
                for (int i = 0; i < 4; i++)
                    As[nb][t][lk + i*4][lm] = ra[t][i];
            #pragma unroll
            for (int i = 0; i < 4; i++) { int e = tid + i*256; Ws[nb][e >> 6][e & 63] = rw[i]; }
        }
        __syncthreads();
        buf ^= 1;
    }

    // unpack to scalar layout acc[t][i*4+j]
    float acc[TT][16];
    #pragma unroll
    for (int t = 0; t < TT; t++)
        #pragma unroll
        for (int p = 0; p < 2; p++)
            #pragma unroll
            for (int j = 0; j < 4; j++) {
                u32 lo, hi;
                UNPACK_F32X2(lo, hi, acc2[t][p][j]);
                acc[t][(2*p)*4 + j]     = __uint_as_float(lo);
                acc[t][(2*p + 1)*4 + j] = __uint_as_float(hi);
            }

    // ---- epilogue: BN + LIF (exact reference op sequence; no fma contraction) ----
    const int tx = tid & 15, ty = tid >> 4;
    int dl = d0 + tx*4;
    const float *sc, *bi;
    if (FINAL) { sc = sc0; bi = bi0; }
    else {
        int ten = d0 / CC;
        dl = d0 - ten*CC + tx*4;
        sc = (ten == 0) ? sc0 : (ten == 1) ? sc1 : sc2;
        bi = (ten == 0) ? bi0 : (ten == 1) ? bi1 : bi2;
    }
    float scv[4], biv[4];
    #pragma unroll
    for (int j = 0; j < 4; j++) { scv[j] = sc[dl + j]; biv[j] = bi[dl + j]; }

    #pragma unroll
    for (int i = 0; i < 4; i++) {
        int m = m0 + ty*4 + i;
        float v[4] = {0.f, 0.f, 0.f, 0.f};
        if (!FINAL) {
            #pragma unroll
            for (int t = 0; t < TT; t++) {
                unsigned pk = 0;
                #pragma unroll
                for (int j = 0; j < 4; j++) {
                    float y = __fadd_rn(__fmul_rn(acc[t][i*4 + j], scv[j]), biv[j]);
                    v[j] = __fadd_rn(v[j], __fmul_rn(__fadd_rn(y, -v[j]), 0.5f));
                    if (v[j] >= 1.0f) { pk |= 1u << (8*j); v[j] = 0.f; }
                }
                *(unsigned*)&g_spk[((size_t)t*MM + m)*DQKV + d0 + tx*4] = pk;
            }
        } else {
            int b_o = m / NN, n_o = m - b_o*NN;
            #pragma unroll
            for (int t = 0; t < TT; t++) {
                #pragma unroll
                for (int j = 0; j < 4; j++) {
                    float y = __fadd_rn(__fmul_rn(acc[t][i*4 + j], scv[j]), biv[j]);
                    v[j] = __fadd_rn(v[j], __fmul_rn(__fadd_rn(y, -v[j]), 0.5f));
                    bool hh = v[j] >= 1.0f;
                    outF[(((size_t)t*BBATCH + b_o)*CC + (dl + j))*NN + n_o] = hh ? 1.0f : 0.0f;
                    if (hh) v[j] = 0.f;
                }
            }
        }
    }
}

// ---------------- attention (pack fused): out = q @ (k^T v) * 0.125, LIF(0.5) ----------------
// Integer-exact: spikes binary, G entries <=196, sums <=9408 < 2^16.
__global__ void __launch_bounds__(256) k_attn() {
    __shared__ unsigned long long qm[TT][NN];
    __shared__ unsigned long long km[TT][NN];
    __shared__ unsigned long long vm[TT][NN];
    __shared__ unsigned int kT[TT][DD][7];
    __shared__ unsigned int vT[TT][DD][7];
    __shared__ __align__(16) unsigned int Gp[TT][DD][24];   // two u16 sums per word

    const int b = blockIdx.x, h = blockIdx.y;
    const int tid = threadIdx.x;

    // ---- pack spike bytes -> 48-bit masks (fused; byte-gather multiply trick) ----
    for (int e = tid; e < 3*TT*NN; e += 256) {
        int ten = e / (TT*NN);
        int r = e - ten*(TT*NN);
        int t = r / NN, n = r - t*NN;
        int m = b*NN + n;
        const uint4* p = (const uint4*)(g_spk + ((size_t)t*MM + m)*DQKV + ten*CC + h*DD);
        unsigned long long mask = 0;
        #pragma unroll
        for (int q = 0; q < 3; q++) {
            uint4 u = p[q];
            unsigned n0 = (u.x * 0x01020408u) >> 24;          // bits 0..3 (garbage above cleared by field width)
            unsigned n1 = (u.y * 0x01020408u) >> 24;
            unsigned n2 = (u.z * 0x01020408u) >> 24;
            unsigned n3 = (u.w * 0x01020408u) >> 24;
            unsigned hw = (n0 & 0xF) | ((n1 & 0xF) << 4) | ((n2 & 0xF) << 8) | ((n3 & 0xF) << 12);
            mask |= (unsigned long long)hw << (16*q);
        }
        if (ten == 0) qm[t][n] = mask;
        else if (ten == 1) km[t][n] = mask;
        else vm[t][n] = mask;
    }
    __syncthreads();

    // ---- bit-transpose k,v via warp ballot: 8 warps = 4 t x {k,v} ----
    {
        int w = tid >> 5, lane = tid & 31;
        int t = w >> 1;
        int isv = w & 1;
        for (int g = 0; g < 7; g++) {
            int m = g*32 + lane;
            unsigned long long mk = 0;
            if (m < NN) mk = isv ? vm[t][m] : km[t][m];
            #pragma unroll
            for (int j = 0; j < DD; j++) {
                unsigned bal = __ballot_sync(0xffffffffu, (unsigned)((mk >> j) & 1ull));
                if (lane == 0) { if (isv) vT[t][j][g] = bal; else kT[t][j][g] = bal; }
            }
        }
    }
    __syncthreads();

    // ---- Gp[t][j][p] = G[j][2p] | G[j][2p+1]<<16 via AND+popc ----
    for (int e = tid; e < TT*DD*24; e += 256) {
        int t = e / (DD*24), r = e - t*(DD*24);
        int j = r / 24, p = r - j*24;
        int s0 = 0, s1 = 0;
        #pragma unroll
        for (int g = 0; g < 7; g++) {
            s0 += __popc(kT[t][j][g] & vT[t][2*p][g]);
            s1 += __popc(kT[t][j][g] & vT[t][2*p + 1][g]);
        }
        Gp[t][j][p] = (unsigned)s0 | ((unsigned)s1 << 16);
    }
    __syncthreads();

    // ---- out[n, 8g..8g+7]: masked packed adds over j; LIF(0.5); write fp32 spikes ----
    for (int e = tid; e < 6*NN; e += 256) {
        int g = e / NN, n = e - g*NN;
        int p0 = g * 4;
        float v[8];
        #pragma unroll
        for (int d = 0; d < 8; d++) v[d] = 0.f;
        #pragma unroll
        for (int t = 0; t < TT; t++) {
            unsigned long long q = qm[t][n];
            unsigned ql = (unsigned)q, qh = (unsigned)(q >> 32);
            unsigned S[4] = {0u, 0u, 0u, 0u};
            #pragma unroll
            for (int j = 0; j < 32; j++) {
                unsigned msk = (unsigned)((int)(ql << (31 - j)) >> 31);
                uint4 gw = *(const uint4*)&Gp[t][j][p0];
                S[0] += gw.x & msk; S[1] += gw.y & msk;
                S[2] += gw.z & msk; S[3] += gw.w & msk;
            }
            #pragma unroll
            for (int j = 0; j < 16; j++) {
                unsigned msk = (unsigned)((int)(qh << (31 - j)) >> 31);
                uint4 gw = *(const uint4*)&Gp[t][32 + j][p0];
                S[0] += gw.x & msk; S[1] += gw.y & msk;
                S[2] += gw.z & msk; S[3] += gw.w & msk;
            }
            float* outp = &g_attnspk[(((size_t)t*BBATCH + b)*CC + h*DD + 8*g)*NN + n];
            #pragma unroll
            for (int pp = 0; pp < 4; pp++) {
                int s0 = (int)(S[pp] & 0xFFFFu);
                int s1 = (int)(S[pp] >> 16);
                float x0 = (float)s0 * 0.125f;
                float x1 = (float)s1 * 0.125f;
                int d0i = 2*pp, d1i = 2*pp + 1;
                v[d0i] = __fadd_rn(v[d0i], __fmul_rn(__fadd_rn(x0, -v[d0i]), 0.5f));
                v[d1i] = __fadd_rn(v[d1i], __fmul_rn(__fadd_rn(x1, -v[d1i]), 0.5f));
                bool h0 = v[d0i] >= 0.5f, h1 = v[d1i] >= 0.5f;
                outp[(size_t)d0i * NN] = h0 ? 1.0f : 0.0f;
                outp[(size_t)d1i * NN] = h1 ? 1.0f : 0.0f;
                if (h0) v[d0i] = 0.f;
                if (h1) v[d1i] = 0.f;
            }
        }
    }
}

// ---------------- launch ----------------
extern "C" void kernel_launch(void* const* d_in, const int* in_sizes, int n_in,
                              void* d_out, int out_size) {
    const float* x  = (const float*)d_in[0];
    const float* wq = (const float*)d_in[1];
    const float* sq = (const float*)d_in[2];
    const float* bq = (const float*)d_in[3];
    const float* wk = (const float*)d_in[4];
    const float* sk = (const float*)d_in[5];
    const float* bk = (const float*)d_in[6];
    const float* wv = (const float*)d_in[7];
    const float* sv = (const float*)d_in[8];
    const float* bv = (const float*)d_in[9];
    const float* wp = (const float*)d_in[10];
    const float* sp = (const float*)d_in[11];
    const float* bp = (const float*)d_in[12];
    float* out = (float*)d_out;

    k_prepw<<<(CC*DQKV + CC*CC + 255)/256, 256>>>(wq, wk, wv, wp);
    k_conv_lif<false><<<dim3(98, 18), 256>>>(x, sq, sk, sv, bq, bk, bv, nullptr);
    k_attn<<<dim3(BBATCH, HH), 256>>>();
    k_conv_lif<true><<<dim3(98, 6), 256>>>(x, sp, sp, sp, bp, bp, bp, out);
}